// round 7
// baseline (speedup 1.0000x reference)
#include <cuda_runtime.h>
#include <cuda_bf16.h>
#include <mma.h>
#include <cstdint>

using namespace nvcuda;

// Problem constants
#define CUR    1024
#define FULL   2048
#define BSZ    4
#define DMODEL 1024
#define HN     16
#define HD     64
#define PREV   (FULL - CUR)      // 1024
#define ZB     (BSZ * HN)        // 64 batched heads
#define SCALE  0.125f            // 1/sqrt(64)

// ---------------------------------------------------------------------------
// Scratch
// ---------------------------------------------------------------------------
__device__ float g_kv [ (size_t)FULL * BSZ * 2 * HN * HD ];   // 8192 x 2048
__device__ float g_q  [ (size_t)CUR * BSZ * HN * HD ];        // 4096 x 1024
__device__ float g_qu [ (size_t)CUR * BSZ * HN * HD ];
__device__ float g_qv [ (size_t)CUR * BSZ * HN * HD ];
__device__ float g_r  [ (size_t)FULL * HN * HD ];             // 2048 x 1024
__device__ float g_ctx[ (size_t)CUR * BSZ * HN * HD ];
__device__ float g_scores[ (size_t)ZB * CUR * FULL ];         // content -> probs
__device__ float g_pos   [ (size_t)ZB * CUR * FULL ];         // unshifted position
__device__ float g_beff[ DMODEL ];

#define TF32(x) wmma::__float_to_tf32(x)

// ---------------------------------------------------------------------------
// TF32 GEMM: C[M,N] = A[M,K] @ B[K,N]  (R2 tiling, odd smem pitches)
// 128x128 tile, KC=32, 256 threads, 8 warps each 64x32.
// ---------------------------------------------------------------------------
#define LDA_G 33
#define LDB_G 129
__global__ __launch_bounds__(256) void gemm_tf32(
    const float* __restrict__ A, const float* __restrict__ B,
    float* __restrict__ C, int M, int N, int K)
{
    __shared__ float sA[128 * LDA_G];   // [m][k] pitch 33
    __shared__ float sB[32 * LDB_G];    // [k][n] pitch 129
    int tid = threadIdx.x, warp = tid >> 5;
    int wm = warp >> 2, wn = warp & 3;
    int m0 = blockIdx.y * 128, n0 = blockIdx.x * 128;

    wmma::fragment<wmma::accumulator, 16, 16, 8, float> acc[4][2];
#pragma unroll
    for (int i = 0; i < 4; i++)
#pragma unroll
        for (int j = 0; j < 2; j++) wmma::fill_fragment(acc[i][j], 0.f);

    int am = tid >> 1,  ak = (tid & 1) * 16;
    int bk = tid >> 3,  bn = (tid & 7) * 16;

    for (int k0 = 0; k0 < K; k0 += 32) {
        const float* ap = A + (size_t)(m0 + am) * K + k0 + ak;
        float* sa = sA + am * LDA_G + ak;
#pragma unroll
        for (int s = 0; s < 4; s++) {
            float4 v = *reinterpret_cast<const float4*>(ap + 4 * s);
            sa[4 * s + 0] = TF32(v.x);
            sa[4 * s + 1] = TF32(v.y);
            sa[4 * s + 2] = TF32(v.z);
            sa[4 * s + 3] = TF32(v.w);
        }
        const float* bp = B + (size_t)(k0 + bk) * N + n0 + bn;
        float* sb = sB + bk * LDB_G + bn;
#pragma unroll
        for (int s = 0; s < 4; s++) {
            float4 v = *reinterpret_cast<const float4*>(bp + 4 * s);
            sb[4 * s + 0] = TF32(v.x);
            sb[4 * s + 1] = TF32(v.y);
            sb[4 * s + 2] = TF32(v.z);
            sb[4 * s + 3] = TF32(v.w);
        }
        __syncthreads();
#pragma unroll
        for (int kk = 0; kk < 4; kk++) {
            wmma::fragment<wmma::matrix_a, 16, 16, 8, wmma::precision::tf32, wmma::row_major> af[4];
            wmma::fragment<wmma::matrix_b, 16, 16, 8, wmma::precision::tf32, wmma::row_major> bf[2];
#pragma unroll
            for (int i = 0; i < 4; i++)
                wmma::load_matrix_sync(af[i], &sA[(wm * 64 + i * 16) * LDA_G + kk * 8], LDA_G);
#pragma unroll
            for (int j = 0; j < 2; j++)
                wmma::load_matrix_sync(bf[j], &sB[(kk * 8) * LDB_G + wn * 32 + j * 16], LDB_G);
#pragma unroll
            for (int i = 0; i < 4; i++)
#pragma unroll
                for (int j = 0; j < 2; j++)
                    wmma::mma_sync(acc[i][j], af[i], bf[j], acc[i][j]);
        }
        __syncthreads();
    }
#pragma unroll
    for (int i = 0; i < 4; i++)
#pragma unroll
        for (int j = 0; j < 2; j++)
            wmma::store_matrix_sync(
                C + (size_t)(m0 + wm * 64 + i * 16) * N + n0 + wn * 32 + j * 16,
                acc[i][j], N, wmma::mem_row_major);
}

// ---------------------------------------------------------------------------
// qu = q + (b_q + u)[n],  qv = q + (b_q + v)[n]
// ---------------------------------------------------------------------------
__global__ __launch_bounds__(256) void quv_kernel(
    const float* __restrict__ q, const float* __restrict__ b_q,
    const float* __restrict__ u, const float* __restrict__ v,
    float* __restrict__ qu, float* __restrict__ qv)
{
    int idx = blockIdx.x * 256 + threadIdx.x;
    int n4 = idx & 255;
    float4 qq = reinterpret_cast<const float4*>(q)[idx];
    float4 bb = reinterpret_cast<const float4*>(b_q)[n4];
    float4 uu = reinterpret_cast<const float4*>(u)[n4];
    float4 vv = reinterpret_cast<const float4*>(v)[n4];
    float4 a, c;
    a.x = qq.x + bb.x + uu.x; a.y = qq.y + bb.y + uu.y;
    a.z = qq.z + bb.z + uu.z; a.w = qq.w + bb.w + uu.w;
    c.x = qq.x + bb.x + vv.x; c.y = qq.y + bb.y + vv.y;
    c.z = qq.z + bb.z + vv.z; c.w = qq.w + bb.w + vv.w;
    reinterpret_cast<float4*>(qu)[idx] = a;
    reinterpret_cast<float4*>(qv)[idx] = c;
}

__global__ __launch_bounds__(256) void beff_kernel(
    const float* __restrict__ b_kv, const float* __restrict__ W_proj,
    const float* __restrict__ b_proj, float* __restrict__ beff)
{
    int n = blockIdx.x * 256 + threadIdx.x;
    float acc = b_proj[n];
    for (int m = 0; m < DMODEL; m++)
        acc += b_kv[DMODEL + m] * W_proj[(size_t)m * DMODEL + n];
    beff[n] = acc;
}

__global__ __launch_bounds__(256) void bias_add_kernel(
    float* __restrict__ out, const float* __restrict__ beff)
{
    int idx = blockIdx.x * 256 + threadIdx.x;
    int n4 = idx & 255;
    float4 o = reinterpret_cast<float4*>(out)[idx];
    float4 b = reinterpret_cast<const float4*>(beff)[n4];
    o.x += b.x; o.y += b.y; o.z += b.z; o.w += b.w;
    reinterpret_cast<float4*>(out)[idx] = o;
}

// ---------------------------------------------------------------------------
// Score GEMM (content or unshifted position), TF32, odd pitches:
//   OUT[z,i,j] = sum_d A(i,d) * B(j,d)
// 128x128 tile, K=64 in chunks of 32; analytic block skips.
// ---------------------------------------------------------------------------
#define LDS_S 33
__global__ __launch_bounds__(256) void score_tf32(
    const float* __restrict__ QU, const float* __restrict__ SRC,
    float* __restrict__ OUT, int isPos)
{
    int i0 = blockIdx.y * 128, j0 = blockIdx.x * 128;
    if (!isPos && j0 >= i0 + 1152) return;                 // all masked
    if (isPos && (i0 + j0 + 254) < 1023) return;           // never read after shift
    int z = blockIdx.z;
    int b = z >> 4, h = z & 15;
    const float* A0 = QU + b * DMODEL + h * HD;            // ld 4096
    const float* B0 = isPos ? (SRC + h * HD) : (SRC + b * 2048 + h * HD);
    size_t ldB = isPos ? (size_t)(HN * HD) : (size_t)(BSZ * 2 * HN * HD);

    __shared__ float sA[128 * LDS_S];
    __shared__ float sB[128 * LDS_S];
    int tid = threadIdx.x, warp = tid >> 5;
    int wm = warp >> 2, wn = warp & 3;

    wmma::fragment<wmma::accumulator, 16, 16, 8, float> acc[4][2];
#pragma unroll
    for (int i = 0; i < 4; i++)
#pragma unroll
        for (int j = 0; j < 2; j++) wmma::fill_fragment(acc[i][j], 0.f);

    int rm = tid >> 1, rk = (tid & 1) * 16;

    for (int d0 = 0; d0 < HD; d0 += 32) {
        const float* ap = A0 + (size_t)(i0 + rm) * (BSZ * DMODEL) + d0 + rk;
        float* sa = sA + rm * LDS_S + rk;
#pragma unroll
        for (int s = 0; s < 4; s++) {
            float4 v = *reinterpret_cast<const float4*>(ap + 4 * s);
            sa[4 * s + 0] = TF32(v.x);
            sa[4 * s + 1] = TF32(v.y);
            sa[4 * s + 2] = TF32(v.z);
            sa[4 * s + 3] = TF32(v.w);
        }
        const float* bp = B0 + (size_t)(j0 + rm) * ldB + d0 + rk;
        float* sb = sB + rm * LDS_S + rk;
#pragma unroll
        for (int s = 0; s < 4; s++) {
            float4 v = *reinterpret_cast<const float4*>(bp + 4 * s);
            sb[4 * s + 0] = TF32(v.x);
            sb[4 * s + 1] = TF32(v.y);
            sb[4 * s + 2] = TF32(v.z);
            sb[4 * s + 3] = TF32(v.w);
        }
        __syncthreads();
#pragma unroll
        for (int kk = 0; kk < 4; kk++) {
            wmma::fragment<wmma::matrix_a, 16, 16, 8, wmma::precision::tf32, wmma::row_major> af[4];
            wmma::fragment<wmma::matrix_b, 16, 16, 8, wmma::precision::tf32, wmma::col_major> bf[2];
#pragma unroll
            for (int i = 0; i < 4; i++)
                wmma::load_matrix_sync(af[i], &sA[(wm * 64 + i * 16) * LDS_S + kk * 8], LDS_S);
#pragma unroll
            for (int j = 0; j < 2; j++)
                wmma::load_matrix_sync(bf[j], &sB[(wn * 32 + j * 16) * LDS_S + kk * 8], LDS_S);
#pragma unroll
            for (int i = 0; i < 4; i++)
#pragma unroll
                for (int j = 0; j < 2; j++)
                    wmma::mma_sync(acc[i][j], af[i], bf[j], acc[i][j]);
        }
        __syncthreads();
    }
    float* C0 = OUT + (size_t)z * CUR * FULL;
#pragma unroll
    for (int i = 0; i < 4; i++)
#pragma unroll
        for (int j = 0; j < 2; j++)
            wmma::store_matrix_sync(
                C0 + (size_t)(i0 + wm * 64 + i * 16) * FULL + j0 + wn * 32 + j * 16,
                acc[i][j], FULL, wmma::mem_row_major);
}

// ---------------------------------------------------------------------------
// Fused rel_shift gather + mask + softmax (in place into g_scores).
// ---------------------------------------------------------------------------
__global__ __launch_bounds__(256) void softmax_kernel(
    const float* __restrict__ cont, const float* __restrict__ pos,
    float* __restrict__ out)
{
    int i = blockIdx.x;
    int z = blockIdx.y;
    int tid = threadIdx.x;
    size_t rowOff = ((size_t)z * CUR + i) * FULL;
    const float* c = cont + rowOff;
    const float* p = pos + rowOff;
    int jmax  = i + PREV;
    int shift = CUR - 1 - i;

    float vals[8];
    float mx = -1e30f;
#pragma unroll
    for (int it = 0; it < 8; it++) {
        int j = tid + it * 256;
        float s = -1e30f;
        if (j <= jmax) s = (c[j] + p[j + shift]) * SCALE;
        vals[it] = s;
        mx = fmaxf(mx, s);
    }
    __shared__ float redm[8];
    __shared__ float reds[8];
#pragma unroll
    for (int o = 16; o; o >>= 1) mx = fmaxf(mx, __shfl_xor_sync(0xffffffffu, mx, o));
    if ((tid & 31) == 0) redm[tid >> 5] = mx;
    __syncthreads();
    mx = redm[0];
#pragma unroll
    for (int w = 1; w < 8; w++) mx = fmaxf(mx, redm[w]);

    float sum = 0.f;
#pragma unroll
    for (int it = 0; it < 8; it++) {
        float e = __expf(vals[it] - mx);
        vals[it] = e;
        sum += e;
    }
#pragma unroll
    for (int o = 16; o; o >>= 1) sum += __shfl_xor_sync(0xffffffffu, sum, o);
    if ((tid & 31) == 0) reds[tid >> 5] = sum;
    __syncthreads();
    sum = 0.f;
#pragma unroll
    for (int w = 0; w < 8; w++) sum += reds[w];
    float inv = 1.f / sum;

    float* o = out + rowOff;
#pragma unroll
    for (int it = 0; it < 8; it++) {
        int j = tid + it * 256;
        o[j] = (j <= jmax) ? vals[it] * inv : 0.f;
    }
}

// ---------------------------------------------------------------------------
// Context GEMM, TF32, odd pitches: ctx = probs @ val, K truncated at i0+1152.
// ---------------------------------------------------------------------------
#define LDA_C 33
#define LDB_C 65
__global__ __launch_bounds__(256) void ctx_tf32(
    const float* __restrict__ probs, const float* __restrict__ kv,
    float* __restrict__ ctx)
{
    int z = blockIdx.y;
    int b = z >> 4, h = z & 15;
    int i0 = blockIdx.x * 128;
    const float* A0 = probs + (size_t)z * CUR * FULL;
    const float* B0 = kv + (size_t)b * 2048 + HN * HD + h * HD;

    __shared__ float sA[128 * LDA_C];
    __shared__ float sB[32 * LDB_C];
    int tid = threadIdx.x, warp = tid >> 5;
    int wm = warp >> 1, wn = warp & 1;

    wmma::fragment<wmma::accumulator, 16, 16, 8, float> acc[2][2];
#pragma unroll
    for (int i = 0; i < 2; i++)
#pragma unroll
        for (int j = 0; j < 2; j++) wmma::fill_fragment(acc[i][j], 0.f);

    int am = tid >> 1, aj = (tid & 1) * 16;
    int bj = tid >> 3, bd = (tid & 7) * 8;

    int kmax = i0 + 1152;  if (kmax > FULL) kmax = FULL;

    for (int k0 = 0; k0 < kmax; k0 += 32) {
        const float* ap = A0 + (size_t)(i0 + am) * FULL + k0 + aj;
        float* sa = sA + am * LDA_C + aj;
#pragma unroll
        for (int s = 0; s < 4; s++) {
            float4 v = *reinterpret_cast<const float4*>(ap + 4 * s);
            sa[4 * s + 0] = TF32(v.x);
            sa[4 * s + 1] = TF32(v.y);
            sa[4 * s + 2] = TF32(v.z);
            sa[4 * s + 3] = TF32(v.w);
        }
        const float* bp = B0 + (size_t)(k0 + bj) * (BSZ * 2 * HN * HD) + bd;
        float* sb = sB + bj * LDB_C + bd;
#pragma unroll
        for (int s = 0; s < 2; s++) {
            float4 v = *reinterpret_cast<const float4*>(bp + 4 * s);
            sb[4 * s + 0] = TF32(v.x);
            sb[4 * s + 1] = TF32(v.y);
            sb[4 * s + 2] = TF32(v.z);
            sb[4 * s + 3] = TF32(v.w);
        }
        __syncthreads();
#pragma unroll
        for (int kk = 0; kk < 4; kk++) {
            wmma::fragment<wmma::matrix_a, 16, 16, 8, wmma::precision::tf32, wmma::row_major> af[2];
            wmma::fragment<wmma::matrix_b, 16, 16, 8, wmma::precision::tf32, wmma::row_major> bf[2];
#pragma unroll
            for (int i = 0; i < 2; i++)
                wmma::load_matrix_sync(af[i], &sA[(wm * 32 + i * 16) * LDA_C + kk * 8], LDA_C);
#pragma unroll
            for (int j = 0; j < 2; j++)
                wmma::load_matrix_sync(bf[j], &sB[(kk * 8) * LDB_C + wn * 32 + j * 16], LDB_C);
#pragma unroll
            for (int i = 0; i < 2; i++)
#pragma unroll
                for (int j = 0; j < 2; j++)
                    wmma::mma_sync(acc[i][j], af[i], bf[j], acc[i][j]);
        }
        __syncthreads();
    }
#pragma unroll
    for (int i = 0; i < 2; i++)
#pragma unroll
        for (int j = 0; j < 2; j++)
            wmma::store_matrix_sync(
                ctx + (size_t)((i0 + wm * 32 + i * 16) * BSZ + b) * DMODEL + h * HD + wn * 32 + j * 16,
                acc[i][j], BSZ * DMODEL, wmma::mem_row_major);
}

// ---------------------------------------------------------------------------
// Launch
// ---------------------------------------------------------------------------
extern "C" void kernel_launch(void* const* d_in, const int* in_sizes, int n_in,
                              void* d_out, int out_size)
{
    const float* inputs  = (const float*)d_in[0];
    const float* pos_emb = (const float*)d_in[1];
    const float* full_in = (const float*)d_in[2];
    const float* u       = (const float*)d_in[3];
    const float* v       = (const float*)d_in[4];
    const float* W_kv    = (const float*)d_in[6];
    const float* b_kv    = (const float*)d_in[7];
    const float* W_q     = (const float*)d_in[8];
    const float* b_q     = (const float*)d_in[9];
    const float* W_pos   = (const float*)d_in[10];
    const float* W_proj  = (const float*)d_in[12];
    const float* b_proj  = (const float*)d_in[13];
    float* out = (float*)d_out;

    float *kv, *q, *qu, *qv, *r, *ctx, *scores, *pos, *beff;
    cudaGetSymbolAddress((void**)&kv,     g_kv);
    cudaGetSymbolAddress((void**)&q,      g_q);
    cudaGetSymbolAddress((void**)&qu,     g_qu);
    cudaGetSymbolAddress((void**)&qv,     g_qv);
    cudaGetSymbolAddress((void**)&r,      g_r);
    cudaGetSymbolAddress((void**)&ctx,    g_ctx);
    cudaGetSymbolAddress((void**)&scores, g_scores);
    cudaGetSymbolAddress((void**)&pos,    g_pos);
    cudaGetSymbolAddress((void**)&beff,   g_beff);

    // Projections (bias-free; biases folded/dropped analytically)
    gemm_tf32<<<dim3(2048 / 128, 8192 / 128), 256>>>(full_in, W_kv, kv, 8192, 2048, 1024);
    gemm_tf32<<<dim3(1024 / 128, 4096 / 128), 256>>>(inputs, W_q, q, 4096, 1024, 1024);
    gemm_tf32<<<dim3(1024 / 128, 2048 / 128), 256>>>(pos_emb, W_pos, r, 2048, 1024, 1024);

    quv_kernel<<<4096, 256>>>(q, b_q, u, v, qu, qv);
    beff_kernel<<<DMODEL / 256, 256>>>(b_kv, W_proj, b_proj, beff);

    // Scores on tensor pipe
    score_tf32<<<dim3(FULL / 128, CUR / 128, ZB), 256>>>(qu, kv, scores, 0);
    score_tf32<<<dim3(FULL / 128, CUR / 128, ZB), 256>>>(qv, r, pos, 1);

    // shift + mask + softmax (in place)
    softmax_kernel<<<dim3(CUR, ZB), 256>>>(scores, pos, scores);

    // ctx = probs @ val
    ctx_tf32<<<dim3(CUR / 128, ZB), 256>>>(scores, kv, ctx);

    // out = ctx @ W_proj + b_eff
    gemm_tf32<<<dim3(1024 / 128, 4096 / 128), 256>>>(ctx, W_proj, out, 4096, 1024, 1024);
    bias_add_kernel<<<4096, 256>>>(out, beff);

    (void)in_sizes; (void)n_in; (void)out_size;
}

// round 9
// speedup vs baseline: 1.6505x; 1.6505x over previous
#include <cuda_runtime.h>
#include <cuda_fp16.h>
#include <mma.h>
#include <cstdint>

using namespace nvcuda;

// Problem constants
#define CUR    1024
#define FULL   2048
#define BSZ    4
#define DMODEL 1024
#define HN     16
#define HD     64
#define PREV   (FULL - CUR)      // 1024
#define ZB     (BSZ * HN)        // 64 batched heads
#define SCALE  0.125f            // 1/sqrt(64)

// ---------------------------------------------------------------------------
// Scratch
// ---------------------------------------------------------------------------
__device__ float  g_kv [ (size_t)FULL * BSZ * 2 * HN * HD ];   // 8192 x 2048
__device__ float  g_q  [ (size_t)CUR * BSZ * HN * HD ];        // 4096 x 1024
__device__ float  g_qu [ (size_t)CUR * BSZ * HN * HD ];
__device__ float  g_qv [ (size_t)CUR * BSZ * HN * HD ];
__device__ float  g_r  [ (size_t)FULL * HN * HD ];             // 2048 x 1024
__device__ float  g_ctx[ (size_t)CUR * BSZ * HN * HD ];
__device__ __half g_scores_h[ (size_t)ZB * CUR * FULL ];       // content (fp16)
__device__ __half g_pos_h   [ (size_t)ZB * CUR * FULL ];       // position (fp16)
__device__ __half g_probs_h [ (size_t)ZB * CUR * FULL ];       // softmax probs (fp16)
__device__ float  g_beff[ DMODEL ];

#define H(x) __float2half_rn(x)

// ---------------------------------------------------------------------------
// FP16 GEMM (fp32 accum): C[M,N] = A[M,K] @ B[K,N]
// 128x128 tile, KC=32, 256 threads, 8 warps each 64x32, m16n16k16.
// ---------------------------------------------------------------------------
__global__ __launch_bounds__(256) void gemm_h(
    const float* __restrict__ A, const float* __restrict__ B,
    float* __restrict__ C, int M, int N, int K)
{
    __shared__ __half sA[128 * 40];    // [m][k] pitch 40
    __shared__ __half sB[32 * 136];    // [k][n] pitch 136
    int tid = threadIdx.x, warp = tid >> 5;
    int wm = warp >> 2, wn = warp & 3;
    int m0 = blockIdx.y * 128, n0 = blockIdx.x * 128;

    wmma::fragment<wmma::accumulator, 16, 16, 16, float> acc[4][2];
#pragma unroll
    for (int i = 0; i < 4; i++)
#pragma unroll
        for (int j = 0; j < 2; j++) wmma::fill_fragment(acc[i][j], 0.f);

    int am = tid >> 1,  ak = (tid & 1) * 16;
    int bk = tid >> 3,  bn = (tid & 7) * 16;

    for (int k0 = 0; k0 < K; k0 += 32) {
        const float* ap = A + (size_t)(m0 + am) * K + k0 + ak;
        __half* sa = sA + am * 40 + ak;
#pragma unroll
        for (int s = 0; s < 4; s++) {
            float4 v = *reinterpret_cast<const float4*>(ap + 4 * s);
            sa[4 * s + 0] = H(v.x); sa[4 * s + 1] = H(v.y);
            sa[4 * s + 2] = H(v.z); sa[4 * s + 3] = H(v.w);
        }
        const float* bp = B + (size_t)(k0 + bk) * N + n0 + bn;
        __half* sb = sB + bk * 136 + bn;
#pragma unroll
        for (int s = 0; s < 4; s++) {
            float4 v = *reinterpret_cast<const float4*>(bp + 4 * s);
            sb[4 * s + 0] = H(v.x); sb[4 * s + 1] = H(v.y);
            sb[4 * s + 2] = H(v.z); sb[4 * s + 3] = H(v.w);
        }
        __syncthreads();
#pragma unroll
        for (int kk = 0; kk < 2; kk++) {
            wmma::fragment<wmma::matrix_a, 16, 16, 16, __half, wmma::row_major> af[4];
            wmma::fragment<wmma::matrix_b, 16, 16, 16, __half, wmma::row_major> bf[2];
#pragma unroll
            for (int i = 0; i < 4; i++)
                wmma::load_matrix_sync(af[i], &sA[(wm * 64 + i * 16) * 40 + kk * 16], 40);
#pragma unroll
            for (int j = 0; j < 2; j++)
                wmma::load_matrix_sync(bf[j], &sB[(kk * 16) * 136 + wn * 32 + j * 16], 136);
#pragma unroll
            for (int i = 0; i < 4; i++)
#pragma unroll
                for (int j = 0; j < 2; j++)
                    wmma::mma_sync(acc[i][j], af[i], bf[j], acc[i][j]);
        }
        __syncthreads();
    }
#pragma unroll
    for (int i = 0; i < 4; i++)
#pragma unroll
        for (int j = 0; j < 2; j++)
            wmma::store_matrix_sync(
                C + (size_t)(m0 + wm * 64 + i * 16) * N + n0 + wn * 32 + j * 16,
                acc[i][j], N, wmma::mem_row_major);
}

// ---------------------------------------------------------------------------
// qu = q + (b_q + u)[n],  qv = q + (b_q + v)[n]
// ---------------------------------------------------------------------------
__global__ __launch_bounds__(256) void quv_kernel(
    const float* __restrict__ q, const float* __restrict__ b_q,
    const float* __restrict__ u, const float* __restrict__ v,
    float* __restrict__ qu, float* __restrict__ qv)
{
    int idx = blockIdx.x * 256 + threadIdx.x;
    int n4 = idx & 255;
    float4 qq = reinterpret_cast<const float4*>(q)[idx];
    float4 bb = reinterpret_cast<const float4*>(b_q)[n4];
    float4 uu = reinterpret_cast<const float4*>(u)[n4];
    float4 vv = reinterpret_cast<const float4*>(v)[n4];
    float4 a, c;
    a.x = qq.x + bb.x + uu.x; a.y = qq.y + bb.y + uu.y;
    a.z = qq.z + bb.z + uu.z; a.w = qq.w + bb.w + uu.w;
    c.x = qq.x + bb.x + vv.x; c.y = qq.y + bb.y + vv.y;
    c.z = qq.z + bb.z + vv.z; c.w = qq.w + bb.w + vv.w;
    reinterpret_cast<float4*>(qu)[idx] = a;
    reinterpret_cast<float4*>(qv)[idx] = c;
}

__global__ __launch_bounds__(256) void beff_kernel(
    const float* __restrict__ b_kv, const float* __restrict__ W_proj,
    const float* __restrict__ b_proj, float* __restrict__ beff)
{
    int n = blockIdx.x * 256 + threadIdx.x;
    float acc = b_proj[n];
    for (int m = 0; m < DMODEL; m++)
        acc += b_kv[DMODEL + m] * W_proj[(size_t)m * DMODEL + n];
    beff[n] = acc;
}

__global__ __launch_bounds__(256) void bias_add_kernel(
    float* __restrict__ out, const float* __restrict__ beff)
{
    int idx = blockIdx.x * 256 + threadIdx.x;
    int n4 = idx & 255;
    float4 o = reinterpret_cast<float4*>(out)[idx];
    float4 b = reinterpret_cast<const float4*>(beff)[n4];
    o.x += b.x; o.y += b.y; o.z += b.z; o.w += b.w;
    reinterpret_cast<float4*>(out)[idx] = o;
}

// ---------------------------------------------------------------------------
// Score GEMM fp16: OUT[z,i,j] = sum_d A(i,d)*B(j,d), output fp16 via smem stage.
// 128x128 tile, K=64 in one shot (kk over 4 k16 chunks). Analytic skips.
// Dynamic smem: fill region (2 x 128x72 half) aliased with stage (128x132 f32).
// ---------------------------------------------------------------------------
#define SCORE_SMEM_BYTES (128 * 132 * 4)
__global__ __launch_bounds__(256) void score_h(
    const float* __restrict__ QU, const float* __restrict__ SRC,
    __half* __restrict__ OUT, int isPos)
{
    int i0 = blockIdx.y * 128, j0 = blockIdx.x * 128;
    if (!isPos && j0 >= i0 + 1152) return;                 // all masked
    if (isPos && (i0 + j0 + 254) < 1023) return;           // never read after shift
    int z = blockIdx.z;
    int b = z >> 4, h = z & 15;
    const float* A0 = QU + b * DMODEL + h * HD;            // ld 4096
    const float* B0 = isPos ? (SRC + h * HD) : (SRC + b * 2048 + h * HD);
    size_t ldB = isPos ? (size_t)(HN * HD) : (size_t)(BSZ * 2 * HN * HD);

    extern __shared__ char dynsm[];
    __half* sA = reinterpret_cast<__half*>(dynsm);           // 128 x 72
    __half* sB = sA + 128 * 72;                              // 128 x 72
    float*  stage = reinterpret_cast<float*>(dynsm);         // 128 x 132 (aliased)

    int tid = threadIdx.x, warp = tid >> 5;
    int wm = warp >> 2, wn = warp & 3;

    wmma::fragment<wmma::accumulator, 16, 16, 16, float> acc[4][2];
#pragma unroll
    for (int i = 0; i < 4; i++)
#pragma unroll
        for (int j = 0; j < 2; j++) wmma::fill_fragment(acc[i][j], 0.f);

    int rm = tid >> 1, rk = (tid & 1) * 32;
    {
        const float* ap = A0 + (size_t)(i0 + rm) * (BSZ * DMODEL) + rk;
        __half* sa = sA + rm * 72 + rk;
#pragma unroll
        for (int s = 0; s < 8; s++) {
            float4 v = *reinterpret_cast<const float4*>(ap + 4 * s);
            sa[4 * s + 0] = H(v.x); sa[4 * s + 1] = H(v.y);
            sa[4 * s + 2] = H(v.z); sa[4 * s + 3] = H(v.w);
        }
        const float* bp = B0 + (size_t)(j0 + rm) * ldB + rk;
        __half* sb = sB + rm * 72 + rk;
#pragma unroll
        for (int s = 0; s < 8; s++) {
            float4 v = *reinterpret_cast<const float4*>(bp + 4 * s);
            sb[4 * s + 0] = H(v.x); sb[4 * s + 1] = H(v.y);
            sb[4 * s + 2] = H(v.z); sb[4 * s + 3] = H(v.w);
        }
    }
    __syncthreads();
#pragma unroll
    for (int kk = 0; kk < 4; kk++) {
        wmma::fragment<wmma::matrix_a, 16, 16, 16, __half, wmma::row_major> af[4];
        wmma::fragment<wmma::matrix_b, 16, 16, 16, __half, wmma::col_major> bf[2];
#pragma unroll
        for (int i = 0; i < 4; i++)
            wmma::load_matrix_sync(af[i], &sA[(wm * 64 + i * 16) * 72 + kk * 16], 72);
#pragma unroll
        for (int j = 0; j < 2; j++)
            wmma::load_matrix_sync(bf[j], &sB[(wn * 32 + j * 16) * 72 + kk * 16], 72);
#pragma unroll
        for (int i = 0; i < 4; i++)
#pragma unroll
            for (int j = 0; j < 2; j++)
                wmma::mma_sync(acc[i][j], af[i], bf[j], acc[i][j]);
    }
    __syncthreads();   // fill region dead; reuse as stage

    // stage fp32 accums, then convert to fp16 global
#pragma unroll
    for (int i = 0; i < 4; i++)
#pragma unroll
        for (int j = 0; j < 2; j++)
            wmma::store_matrix_sync(&stage[(wm * 64 + i * 16) * 132 + wn * 32 + j * 16],
                                    acc[i][j], 132, wmma::mem_row_major);
    __syncthreads();

    __half* C0 = OUT + (size_t)z * CUR * FULL;
    int row = tid >> 1, cb = (tid & 1) * 64;
    __half* dst = C0 + (size_t)(i0 + row) * FULL + j0 + cb;
    const float* src = stage + row * 132 + cb;
#pragma unroll
    for (int t = 0; t < 64; t += 2)
        *reinterpret_cast<__half2*>(dst + t) = __floats2half2_rn(src[t], src[t + 1]);
}

// ---------------------------------------------------------------------------
// Fused rel_shift gather + mask + softmax: fp16 in, fp16 probs out.
// ---------------------------------------------------------------------------
__global__ __launch_bounds__(256) void softmax_kernel(
    const __half* __restrict__ cont, const __half* __restrict__ pos,
    __half* __restrict__ out)
{
    int i = blockIdx.x;
    int z = blockIdx.y;
    int tid = threadIdx.x;
    size_t rowOff = ((size_t)z * CUR + i) * FULL;
    const __half* c = cont + rowOff;
    const __half* p = pos + rowOff;
    int jmax  = i + PREV;
    int shift = CUR - 1 - i;

    float vals[8];
    float mx = -1e30f;
#pragma unroll
    for (int it = 0; it < 8; it++) {
        int j = tid + it * 256;
        float s = -1e30f;
        if (j <= jmax)
            s = (__half2float(c[j]) + __half2float(p[j + shift])) * SCALE;
        vals[it] = s;
        mx = fmaxf(mx, s);
    }
    __shared__ float redm[8];
    __shared__ float reds[8];
#pragma unroll
    for (int o = 16; o; o >>= 1) mx = fmaxf(mx, __shfl_xor_sync(0xffffffffu, mx, o));
    if ((tid & 31) == 0) redm[tid >> 5] = mx;
    __syncthreads();
    mx = redm[0];
#pragma unroll
    for (int w = 1; w < 8; w++) mx = fmaxf(mx, redm[w]);

    float sum = 0.f;
#pragma unroll
    for (int it = 0; it < 8; it++) {
        float e = __expf(vals[it] - mx);
        vals[it] = e;
        sum += e;
    }
#pragma unroll
    for (int o = 16; o; o >>= 1) sum += __shfl_xor_sync(0xffffffffu, sum, o);
    if ((tid & 31) == 0) reds[tid >> 5] = sum;
    __syncthreads();
    sum = 0.f;
#pragma unroll
    for (int w = 0; w < 8; w++) sum += reds[w];
    float inv = 1.f / sum;

    __half* o = out + rowOff;
#pragma unroll
    for (int it = 0; it < 8; it++) {
        int j = tid + it * 256;
        o[j] = (j <= jmax) ? H(vals[it] * inv) : __half(0.f);
    }
}

// ---------------------------------------------------------------------------
// Context GEMM fp16: ctx = probs(fp16) @ val(fp32->h), K truncated at i0+1152.
// Block 128(i) x 64(d), KC=32.
// ---------------------------------------------------------------------------
__global__ __launch_bounds__(256) void ctx_h(
    const __half* __restrict__ probs, const float* __restrict__ kv,
    float* __restrict__ ctx)
{
    int z = blockIdx.y;
    int b = z >> 4, h = z & 15;
    int i0 = blockIdx.x * 128;
    const __half* A0 = probs + (size_t)z * CUR * FULL;
    const float*  B0 = kv + (size_t)b * 2048 + HN * HD + h * HD;

    __shared__ __half sA[128 * 40];   // [i][j] pitch 40
    __shared__ __half sB[32 * 72];    // [j][d] pitch 72
    int tid = threadIdx.x, warp = tid >> 5;
    int wm = warp >> 1, wn = warp & 1;

    wmma::fragment<wmma::accumulator, 16, 16, 16, float> acc[2][2];
#pragma unroll
    for (int i = 0; i < 2; i++)
#pragma unroll
        for (int j = 0; j < 2; j++) wmma::fill_fragment(acc[i][j], 0.f);

    int am = tid >> 1, aj = (tid & 1) * 16;   // 16 halves (32B) per thread
    int bj = tid >> 3, bd = (tid & 7) * 8;

    int kmax = i0 + 1152;  if (kmax > FULL) kmax = FULL;

    for (int k0 = 0; k0 < kmax; k0 += 32) {
        // probs already fp16: copy 16 halves = 2 x uint4 per thread
        const __half* ap = A0 + (size_t)(i0 + am) * FULL + k0 + aj;
        __half* sa = sA + am * 40 + aj;
        *reinterpret_cast<uint4*>(sa)     = *reinterpret_cast<const uint4*>(ap);
        *reinterpret_cast<uint4*>(sa + 8) = *reinterpret_cast<const uint4*>(ap + 8);
        const float* bp = B0 + (size_t)(k0 + bj) * (BSZ * 2 * HN * HD) + bd;
        __half* sb = sB + bj * 72 + bd;
#pragma unroll
        for (int s = 0; s < 2; s++) {
            float4 v = *reinterpret_cast<const float4*>(bp + 4 * s);
            sb[4 * s + 0] = H(v.x); sb[4 * s + 1] = H(v.y);
            sb[4 * s + 2] = H(v.z); sb[4 * s + 3] = H(v.w);
        }
        __syncthreads();
#pragma unroll
        for (int kk = 0; kk < 2; kk++) {
            wmma::fragment<wmma::matrix_a, 16, 16, 16, __half, wmma::row_major> af[2];
            wmma::fragment<wmma::matrix_b, 16, 16, 16, __half, wmma::row_major> bf[2];
#pragma unroll
            for (int i = 0; i < 2; i++)
                wmma::load_matrix_sync(af[i], &sA[(wm * 32 + i * 16) * 40 + kk * 16], 40);
#pragma unroll
            for (int j = 0; j < 2; j++)
                wmma::load_matrix_sync(bf[j], &sB[(kk * 16) * 72 + wn * 32 + j * 16], 72);
#pragma unroll
            for (int i = 0; i < 2; i++)
#pragma unroll
                for (int j = 0; j < 2; j++)
                    wmma::mma_sync(acc[i][j], af[i], bf[j], acc[i][j]);
        }
        __syncthreads();
    }
#pragma unroll
    for (int i = 0; i < 2; i++)
#pragma unroll
        for (int j = 0; j < 2; j++)
            wmma::store_matrix_sync(
                ctx + (size_t)((i0 + wm * 32 + i * 16) * BSZ + b) * DMODEL + h * HD + wn * 32 + j * 16,
                acc[i][j], BSZ * DMODEL, wmma::mem_row_major);
}

// ---------------------------------------------------------------------------
// Launch
// ---------------------------------------------------------------------------
extern "C" void kernel_launch(void* const* d_in, const int* in_sizes, int n_in,
                              void* d_out, int out_size)
{
    const float* inputs  = (const float*)d_in[0];
    const float* pos_emb = (const float*)d_in[1];
    const float* full_in = (const float*)d_in[2];
    const float* u       = (const float*)d_in[3];
    const float* v       = (const float*)d_in[4];
    const float* W_kv    = (const float*)d_in[6];
    const float* b_kv    = (const float*)d_in[7];
    const float* W_q     = (const float*)d_in[8];
    const float* b_q     = (const float*)d_in[9];
    const float* W_pos   = (const float*)d_in[10];
    const float* W_proj  = (const float*)d_in[12];
    const float* b_proj  = (const float*)d_in[13];
    float* out = (float*)d_out;

    float *kv, *q, *qu, *qv, *r, *ctx, *beff;
    __half *scores, *pos, *probs;
    cudaGetSymbolAddress((void**)&kv,     g_kv);
    cudaGetSymbolAddress((void**)&q,      g_q);
    cudaGetSymbolAddress((void**)&qu,     g_qu);
    cudaGetSymbolAddress((void**)&qv,     g_qv);
    cudaGetSymbolAddress((void**)&r,      g_r);
    cudaGetSymbolAddress((void**)&ctx,    g_ctx);
    cudaGetSymbolAddress((void**)&scores, g_scores_h);
    cudaGetSymbolAddress((void**)&pos,    g_pos_h);
    cudaGetSymbolAddress((void**)&probs,  g_probs_h);
    cudaGetSymbolAddress((void**)&beff,   g_beff);

    static int attr_set = 0;
    if (!attr_set) {
        cudaFuncSetAttribute(score_h, cudaFuncAttributeMaxDynamicSharedMemorySize,
                             SCORE_SMEM_BYTES);
        attr_set = 1;
    }

    // Projections (bias-free; biases folded/dropped analytically)
    gemm_h<<<dim3(2048 / 128, 8192 / 128), 256>>>(full_in, W_kv, kv, 8192, 2048, 1024);
    gemm_h<<<dim3(1024 / 128, 4096 / 128), 256>>>(inputs, W_q, q, 4096, 1024, 1024);
    gemm_h<<<dim3(1024 / 128, 2048 / 128), 256>>>(pos_emb, W_pos, r, 2048, 1024, 1024);

    quv_kernel<<<4096, 256>>>(q, b_q, u, v, qu, qv);
    beff_kernel<<<DMODEL / 256, 256>>>(b_kv, W_proj, b_proj, beff);

    // Scores on tensor pipe (fp16 outputs)
    score_h<<<dim3(FULL / 128, CUR / 128, ZB), 256, SCORE_SMEM_BYTES>>>(qu, kv, scores, 0);
    score_h<<<dim3(FULL / 128, CUR / 128, ZB), 256, SCORE_SMEM_BYTES>>>(qv, r, pos, 1);

    // shift + mask + softmax -> fp16 probs
    softmax_kernel<<<dim3(CUR, ZB), 256>>>(scores, pos, probs);

    // ctx = probs @ val
    ctx_h<<<dim3(CUR / 128, ZB), 256>>>(probs, kv, ctx);

    // out = ctx @ W_proj + b_eff
    gemm_h<<<dim3(1024 / 128, 4096 / 128), 256>>>(ctx, W_proj, out, 4096, 1024, 1024);
    bias_add_kernel<<<4096, 256>>>(out, beff);

    (void)in_sizes; (void)n_in; (void)out_size;
}

// round 10
// speedup vs baseline: 1.7756x; 1.0758x over previous
#include <cuda_runtime.h>
#include <cuda_fp16.h>
#include <mma.h>
#include <cstdint>

using namespace nvcuda;

// Problem constants
#define CUR    1024
#define FULL   2048
#define BSZ    4
#define DMODEL 1024
#define HN     16
#define HD     64
#define PREV   (FULL - CUR)      // 1024
#define ZB     (BSZ * HN)        // 64 batched heads
#define SCALE  0.125f            // 1/sqrt(64)

// ---------------------------------------------------------------------------
// Scratch (fp16 intermediates; fp32 only where the next op needs it)
// ---------------------------------------------------------------------------
__device__ __half g_kv [ (size_t)FULL * BSZ * 2 * HN * HD ];   // 8192 x 2048 fp16
__device__ float  g_q  [ (size_t)CUR * BSZ * HN * HD ];        // fp32 (pre-bias)
__device__ __half g_qu [ (size_t)CUR * BSZ * HN * HD ];
__device__ __half g_qv [ (size_t)CUR * BSZ * HN * HD ];
__device__ __half g_r  [ (size_t)FULL * HN * HD ];             // 2048 x 1024 fp16
__device__ __half g_ctx[ (size_t)CUR * BSZ * HN * HD ];
__device__ __half g_scores_h[ (size_t)ZB * CUR * FULL ];
__device__ __half g_pos_h   [ (size_t)ZB * CUR * FULL ];
__device__ __half g_probs_h [ (size_t)ZB * CUR * FULL ];
__device__ float  g_beff[ DMODEL ];

#define H(x) __float2half_rn(x)

// ---------------------------------------------------------------------------
// FP16 GEMM, fp32 A/B inputs, fp32 C: C[M,N] = A[M,K] @ B[K,N]
// 128x128 tile, KC=32, 8 warps each 64x32, m16n16k16.  (R9 winner)
// ---------------------------------------------------------------------------
__global__ __launch_bounds__(256) void gemm_f2f(
    const float* __restrict__ A, const float* __restrict__ B,
    float* __restrict__ C, int M, int N, int K)
{
    __shared__ __half sA[128 * 40];
    __shared__ __half sB[32 * 136];
    int tid = threadIdx.x, warp = tid >> 5;
    int wm = warp >> 2, wn = warp & 3;
    int m0 = blockIdx.y * 128, n0 = blockIdx.x * 128;

    wmma::fragment<wmma::accumulator, 16, 16, 16, float> acc[4][2];
#pragma unroll
    for (int i = 0; i < 4; i++)
#pragma unroll
        for (int j = 0; j < 2; j++) wmma::fill_fragment(acc[i][j], 0.f);

    int am = tid >> 1,  ak = (tid & 1) * 16;
    int bk = tid >> 3,  bn = (tid & 7) * 16;

    for (int k0 = 0; k0 < K; k0 += 32) {
        const float* ap = A + (size_t)(m0 + am) * K + k0 + ak;
        __half* sa = sA + am * 40 + ak;
#pragma unroll
        for (int s = 0; s < 4; s++) {
            float4 v = *reinterpret_cast<const float4*>(ap + 4 * s);
            sa[4 * s + 0] = H(v.x); sa[4 * s + 1] = H(v.y);
            sa[4 * s + 2] = H(v.z); sa[4 * s + 3] = H(v.w);
        }
        const float* bp = B + (size_t)(k0 + bk) * N + n0 + bn;
        __half* sb = sB + bk * 136 + bn;
#pragma unroll
        for (int s = 0; s < 4; s++) {
            float4 v = *reinterpret_cast<const float4*>(bp + 4 * s);
            sb[4 * s + 0] = H(v.x); sb[4 * s + 1] = H(v.y);
            sb[4 * s + 2] = H(v.z); sb[4 * s + 3] = H(v.w);
        }
        __syncthreads();
#pragma unroll
        for (int kk = 0; kk < 2; kk++) {
            wmma::fragment<wmma::matrix_a, 16, 16, 16, __half, wmma::row_major> af[4];
            wmma::fragment<wmma::matrix_b, 16, 16, 16, __half, wmma::row_major> bf[2];
#pragma unroll
            for (int i = 0; i < 4; i++)
                wmma::load_matrix_sync(af[i], &sA[(wm * 64 + i * 16) * 40 + kk * 16], 40);
#pragma unroll
            for (int j = 0; j < 2; j++)
                wmma::load_matrix_sync(bf[j], &sB[(kk * 16) * 136 + wn * 32 + j * 16], 136);
#pragma unroll
            for (int i = 0; i < 4; i++)
#pragma unroll
                for (int j = 0; j < 2; j++)
                    wmma::mma_sync(acc[i][j], af[i], bf[j], acc[i][j]);
        }
        __syncthreads();
    }
#pragma unroll
    for (int i = 0; i < 4; i++)
#pragma unroll
        for (int j = 0; j < 2; j++)
            wmma::store_matrix_sync(
                C + (size_t)(m0 + wm * 64 + i * 16) * N + n0 + wn * 32 + j * 16,
                acc[i][j], N, wmma::mem_row_major);
}

// ---------------------------------------------------------------------------
// Same GEMM but fp16 output via per-warp smem staging.
// ---------------------------------------------------------------------------
__global__ __launch_bounds__(256) void gemm_f2h(
    const float* __restrict__ A, const float* __restrict__ B,
    __half* __restrict__ C, int M, int N, int K)
{
    __shared__ __half sA[128 * 40];
    __shared__ __half sB[32 * 136];
    __shared__ float  stg[8][256];
    int tid = threadIdx.x, warp = tid >> 5, lid = tid & 31;
    int wm = warp >> 2, wn = warp & 3;
    int m0 = blockIdx.y * 128, n0 = blockIdx.x * 128;

    wmma::fragment<wmma::accumulator, 16, 16, 16, float> acc[4][2];
#pragma unroll
    for (int i = 0; i < 4; i++)
#pragma unroll
        for (int j = 0; j < 2; j++) wmma::fill_fragment(acc[i][j], 0.f);

    int am = tid >> 1,  ak = (tid & 1) * 16;
    int bk = tid >> 3,  bn = (tid & 7) * 16;

    for (int k0 = 0; k0 < K; k0 += 32) {
        const float* ap = A + (size_t)(m0 + am) * K + k0 + ak;
        __half* sa = sA + am * 40 + ak;
#pragma unroll
        for (int s = 0; s < 4; s++) {
            float4 v = *reinterpret_cast<const float4*>(ap + 4 * s);
            sa[4 * s + 0] = H(v.x); sa[4 * s + 1] = H(v.y);
            sa[4 * s + 2] = H(v.z); sa[4 * s + 3] = H(v.w);
        }
        const float* bp = B + (size_t)(k0 + bk) * N + n0 + bn;
        __half* sb = sB + bk * 136 + bn;
#pragma unroll
        for (int s = 0; s < 4; s++) {
            float4 v = *reinterpret_cast<const float4*>(bp + 4 * s);
            sb[4 * s + 0] = H(v.x); sb[4 * s + 1] = H(v.y);
            sb[4 * s + 2] = H(v.z); sb[4 * s + 3] = H(v.w);
        }
        __syncthreads();
#pragma unroll
        for (int kk = 0; kk < 2; kk++) {
            wmma::fragment<wmma::matrix_a, 16, 16, 16, __half, wmma::row_major> af[4];
            wmma::fragment<wmma::matrix_b, 16, 16, 16, __half, wmma::row_major> bf[2];
#pragma unroll
            for (int i = 0; i < 4; i++)
                wmma::load_matrix_sync(af[i], &sA[(wm * 64 + i * 16) * 40 + kk * 16], 40);
#pragma unroll
            for (int j = 0; j < 2; j++)
                wmma::load_matrix_sync(bf[j], &sB[(kk * 16) * 136 + wn * 32 + j * 16], 136);
#pragma unroll
            for (int i = 0; i < 4; i++)
#pragma unroll
                for (int j = 0; j < 2; j++)
                    wmma::mma_sync(acc[i][j], af[i], bf[j], acc[i][j]);
        }
        __syncthreads();
    }
    // fp16 epilogue: stage each 16x16 frag through warp-private smem
    int rr = lid >> 1, cc = (lid & 1) * 8;
#pragma unroll
    for (int i = 0; i < 4; i++)
#pragma unroll
        for (int j = 0; j < 2; j++) {
            wmma::store_matrix_sync(&stg[warp][0], acc[i][j], 16, wmma::mem_row_major);
            __syncwarp();
            const float* src = &stg[warp][rr * 16 + cc];
            __half* dst = C + (size_t)(m0 + wm * 64 + i * 16 + rr) * N
                            + n0 + wn * 32 + j * 16 + cc;
#pragma unroll
            for (int t = 0; t < 8; t += 2)
                *reinterpret_cast<__half2*>(dst + t) = __floats2half2_rn(src[t], src[t + 1]);
            __syncwarp();
        }
}

// ---------------------------------------------------------------------------
// Final GEMM: A fp16 (ctx), B fp32 (W_proj), C fp32 (out)
// ---------------------------------------------------------------------------
__global__ __launch_bounds__(256) void gemm_h2f(
    const __half* __restrict__ A, const float* __restrict__ B,
    float* __restrict__ C, int M, int N, int K)
{
    __shared__ __half sA[128 * 40];
    __shared__ __half sB[32 * 136];
    int tid = threadIdx.x, warp = tid >> 5;
    int wm = warp >> 2, wn = warp & 3;
    int m0 = blockIdx.y * 128, n0 = blockIdx.x * 128;

    wmma::fragment<wmma::accumulator, 16, 16, 16, float> acc[4][2];
#pragma unroll
    for (int i = 0; i < 4; i++)
#pragma unroll
        for (int j = 0; j < 2; j++) wmma::fill_fragment(acc[i][j], 0.f);

    int am = tid >> 1,  ak = (tid & 1) * 16;
    int bk = tid >> 3,  bn = (tid & 7) * 16;

    for (int k0 = 0; k0 < K; k0 += 32) {
        const __half* ap = A + (size_t)(m0 + am) * K + k0 + ak;
        __half* sa = sA + am * 40 + ak;
        *reinterpret_cast<uint4*>(sa)     = *reinterpret_cast<const uint4*>(ap);
        *reinterpret_cast<uint4*>(sa + 8) = *reinterpret_cast<const uint4*>(ap + 8);
        const float* bp = B + (size_t)(k0 + bk) * N + n0 + bn;
        __half* sb = sB + bk * 136 + bn;
#pragma unroll
        for (int s = 0; s < 4; s++) {
            float4 v = *reinterpret_cast<const float4*>(bp + 4 * s);
            sb[4 * s + 0] = H(v.x); sb[4 * s + 1] = H(v.y);
            sb[4 * s + 2] = H(v.z); sb[4 * s + 3] = H(v.w);
        }
        __syncthreads();
#pragma unroll
        for (int kk = 0; kk < 2; kk++) {
            wmma::fragment<wmma::matrix_a, 16, 16, 16, __half, wmma::row_major> af[4];
            wmma::fragment<wmma::matrix_b, 16, 16, 16, __half, wmma::row_major> bf[2];
#pragma unroll
            for (int i = 0; i < 4; i++)
                wmma::load_matrix_sync(af[i], &sA[(wm * 64 + i * 16) * 40 + kk * 16], 40);
#pragma unroll
            for (int j = 0; j < 2; j++)
                wmma::load_matrix_sync(bf[j], &sB[(kk * 16) * 136 + wn * 32 + j * 16], 136);
#pragma unroll
            for (int i = 0; i < 4; i++)
#pragma unroll
                for (int j = 0; j < 2; j++)
                    wmma::mma_sync(acc[i][j], af[i], bf[j], acc[i][j]);
        }
        __syncthreads();
    }
#pragma unroll
    for (int i = 0; i < 4; i++)
#pragma unroll
        for (int j = 0; j < 2; j++)
            wmma::store_matrix_sync(
                C + (size_t)(m0 + wm * 64 + i * 16) * N + n0 + wn * 32 + j * 16,
                acc[i][j], N, wmma::mem_row_major);
}

// ---------------------------------------------------------------------------
// qu = q + (b_q + u)[n],  qv = q + (b_q + v)[n]  (fp32 add, fp16 out)
// ---------------------------------------------------------------------------
__global__ __launch_bounds__(256) void quv_kernel(
    const float* __restrict__ q, const float* __restrict__ b_q,
    const float* __restrict__ u, const float* __restrict__ v,
    __half* __restrict__ qu, __half* __restrict__ qv)
{
    int idx = blockIdx.x * 256 + threadIdx.x;          // float4 index
    int n4 = idx & 255;
    float4 qq = reinterpret_cast<const float4*>(q)[idx];
    float4 bb = reinterpret_cast<const float4*>(b_q)[n4];
    float4 uu = reinterpret_cast<const float4*>(u)[n4];
    float4 vv = reinterpret_cast<const float4*>(v)[n4];
    __half2 a0 = __floats2half2_rn(qq.x + bb.x + uu.x, qq.y + bb.y + uu.y);
    __half2 a1 = __floats2half2_rn(qq.z + bb.z + uu.z, qq.w + bb.w + uu.w);
    __half2 c0 = __floats2half2_rn(qq.x + bb.x + vv.x, qq.y + bb.y + vv.y);
    __half2 c1 = __floats2half2_rn(qq.z + bb.z + vv.z, qq.w + bb.w + vv.w);
    reinterpret_cast<__half2*>(qu)[idx * 2 + 0] = a0;
    reinterpret_cast<__half2*>(qu)[idx * 2 + 1] = a1;
    reinterpret_cast<__half2*>(qv)[idx * 2 + 0] = c0;
    reinterpret_cast<__half2*>(qv)[idx * 2 + 1] = c1;
}

__global__ __launch_bounds__(256) void beff_kernel(
    const float* __restrict__ b_kv, const float* __restrict__ W_proj,
    const float* __restrict__ b_proj, float* __restrict__ beff)
{
    int n = blockIdx.x * 256 + threadIdx.x;
    float acc = b_proj[n];
    for (int m = 0; m < DMODEL; m++)
        acc += b_kv[DMODEL + m] * W_proj[(size_t)m * DMODEL + n];
    beff[n] = acc;
}

__global__ __launch_bounds__(256) void bias_add_kernel(
    float* __restrict__ out, const float* __restrict__ beff)
{
    int idx = blockIdx.x * 256 + threadIdx.x;
    int n4 = idx & 255;
    float4 o = reinterpret_cast<float4*>(out)[idx];
    float4 b = reinterpret_cast<const float4*>(beff)[n4];
    o.x += b.x; o.y += b.y; o.z += b.z; o.w += b.w;
    reinterpret_cast<float4*>(out)[idx] = o;
}

// ---------------------------------------------------------------------------
// Score GEMM fp16 (all-fp16 inputs, direct copies): OUT = A @ B^T, fp16 out.
// 128x128 tile, K=64 single-shot. Analytic skips.
// ---------------------------------------------------------------------------
#define SCORE_SMEM_BYTES (128 * 132 * 4)
__global__ __launch_bounds__(256) void score_h(
    const __half* __restrict__ QU, const __half* __restrict__ SRC,
    __half* __restrict__ OUT, int isPos)
{
    int i0 = blockIdx.y * 128, j0 = blockIdx.x * 128;
    if (!isPos && j0 >= i0 + 1152) return;
    if (isPos && (i0 + j0 + 254) < 1023) return;
    int z = blockIdx.z;
    int b = z >> 4, h = z & 15;
    const __half* A0 = QU + b * DMODEL + h * HD;           // ld 4096
    const __half* B0 = isPos ? (SRC + h * HD) : (SRC + b * 2048 + h * HD);
    size_t ldB = isPos ? (size_t)(HN * HD) : (size_t)(BSZ * 2 * HN * HD);

    extern __shared__ char dynsm[];
    __half* sA = reinterpret_cast<__half*>(dynsm);           // 128 x 72
    __half* sB = sA + 128 * 72;                              // 128 x 72
    float*  stage = reinterpret_cast<float*>(dynsm);         // aliased

    int tid = threadIdx.x, warp = tid >> 5;
    int wm = warp >> 2, wn = warp & 3;

    wmma::fragment<wmma::accumulator, 16, 16, 16, float> acc[4][2];
#pragma unroll
    for (int i = 0; i < 4; i++)
#pragma unroll
        for (int j = 0; j < 2; j++) wmma::fill_fragment(acc[i][j], 0.f);

    int rm = tid >> 1, rk = (tid & 1) * 32;   // 32 halves = 4 uint4
    {
        const __half* ap = A0 + (size_t)(i0 + rm) * (BSZ * DMODEL) + rk;
        __half* sa = sA + rm * 72 + rk;
#pragma unroll
        for (int s = 0; s < 4; s++)
            *reinterpret_cast<uint4*>(sa + 8 * s) = *reinterpret_cast<const uint4*>(ap + 8 * s);
        const __half* bp = B0 + (size_t)(j0 + rm) * ldB + rk;
        __half* sb = sB + rm * 72 + rk;
#pragma unroll
        for (int s = 0; s < 4; s++)
            *reinterpret_cast<uint4*>(sb + 8 * s) = *reinterpret_cast<const uint4*>(bp + 8 * s);
    }
    __syncthreads();
#pragma unroll
    for (int kk = 0; kk < 4; kk++) {
        wmma::fragment<wmma::matrix_a, 16, 16, 16, __half, wmma::row_major> af[4];
        wmma::fragment<wmma::matrix_b, 16, 16, 16, __half, wmma::col_major> bf[2];
#pragma unroll
        for (int i = 0; i < 4; i++)
            wmma::load_matrix_sync(af[i], &sA[(wm * 64 + i * 16) * 72 + kk * 16], 72);
#pragma unroll
        for (int j = 0; j < 2; j++)
            wmma::load_matrix_sync(bf[j], &sB[(wn * 32 + j * 16) * 72 + kk * 16], 72);
#pragma unroll
        for (int i = 0; i < 4; i++)
#pragma unroll
            for (int j = 0; j < 2; j++)
                wmma::mma_sync(acc[i][j], af[i], bf[j], acc[i][j]);
    }
    __syncthreads();

#pragma unroll
    for (int i = 0; i < 4; i++)
#pragma unroll
        for (int j = 0; j < 2; j++)
            wmma::store_matrix_sync(&stage[(wm * 64 + i * 16) * 132 + wn * 32 + j * 16],
                                    acc[i][j], 132, wmma::mem_row_major);
    __syncthreads();

    __half* C0 = OUT + (size_t)z * CUR * FULL;
    int row = tid >> 1, cb = (tid & 1) * 64;
    __half* dst = C0 + (size_t)(i0 + row) * FULL + j0 + cb;
    const float* src = stage + row * 132 + cb;
#pragma unroll
    for (int t = 0; t < 64; t += 2)
        *reinterpret_cast<__half2*>(dst + t) = __floats2half2_rn(src[t], src[t + 1]);
}

// ---------------------------------------------------------------------------
// Fused rel_shift gather + mask + softmax: fp16 in, fp16 probs out.
// ---------------------------------------------------------------------------
__global__ __launch_bounds__(256) void softmax_kernel(
    const __half* __restrict__ cont, const __half* __restrict__ pos,
    __half* __restrict__ out)
{
    int i = blockIdx.x;
    int z = blockIdx.y;
    int tid = threadIdx.x;
    size_t rowOff = ((size_t)z * CUR + i) * FULL;
    const __half* c = cont + rowOff;
    const __half* p = pos + rowOff;
    int jmax  = i + PREV;
    int shift = CUR - 1 - i;

    float vals[8];
    float mx = -1e30f;
#pragma unroll
    for (int it = 0; it < 8; it++) {
        int j = tid + it * 256;
        float s = -1e30f;
        if (j <= jmax)
            s = (__half2float(c[j]) + __half2float(p[j + shift])) * SCALE;
        vals[it] = s;
        mx = fmaxf(mx, s);
    }
    __shared__ float redm[8];
    __shared__ float reds[8];
#pragma unroll
    for (int o = 16; o; o >>= 1) mx = fmaxf(mx, __shfl_xor_sync(0xffffffffu, mx, o));
    if ((tid & 31) == 0) redm[tid >> 5] = mx;
    __syncthreads();
    mx = redm[0];
#pragma unroll
    for (int w = 1; w < 8; w++) mx = fmaxf(mx, redm[w]);

    float sum = 0.f;
#pragma unroll
    for (int it = 0; it < 8; it++) {
        float e = __expf(vals[it] - mx);
        vals[it] = e;
        sum += e;
    }
#pragma unroll
    for (int o = 16; o; o >>= 1) sum += __shfl_xor_sync(0xffffffffu, sum, o);
    if ((tid & 31) == 0) reds[tid >> 5] = sum;
    __syncthreads();
    sum = 0.f;
#pragma unroll
    for (int w = 0; w < 8; w++) sum += reds[w];
    float inv = 1.f / sum;

    __half* o = out + rowOff;
#pragma unroll
    for (int it = 0; it < 8; it++) {
        int j = tid + it * 256;
        o[j] = (j <= jmax) ? H(vals[it] * inv) : __half(0.f);
    }
}

// ---------------------------------------------------------------------------
// Context GEMM fp16 in / fp16 out: ctx = probs @ val, K truncated at i0+1152.
// Block 128(i) x 64(d), KC=32.
// ---------------------------------------------------------------------------
__global__ __launch_bounds__(256) void ctx_h(
    const __half* __restrict__ probs, const __half* __restrict__ kv,
    __half* __restrict__ ctx)
{
    int z = blockIdx.y;
    int b = z >> 4, h = z & 15;
    int i0 = blockIdx.x * 128;
    const __half* A0 = probs + (size_t)z * CUR * FULL;
    const __half* B0 = kv + (size_t)b * 2048 + DMODEL + h * HD;

    __shared__ __half sA[128 * 40];
    __shared__ __half sB[32 * 72];
    __shared__ float  stg[8][256];
    int tid = threadIdx.x, warp = tid >> 5, lid = tid & 31;
    int wm = warp >> 1, wn = warp & 1;

    wmma::fragment<wmma::accumulator, 16, 16, 16, float> acc[2][2];
#pragma unroll
    for (int i = 0; i < 2; i++)
#pragma unroll
        for (int j = 0; j < 2; j++) wmma::fill_fragment(acc[i][j], 0.f);

    int am = tid >> 1, aj = (tid & 1) * 16;
    int bj = tid >> 3, bd = (tid & 7) * 8;

    int kmax = i0 + 1152;  if (kmax > FULL) kmax = FULL;

    for (int k0 = 0; k0 < kmax; k0 += 32) {
        const __half* ap = A0 + (size_t)(i0 + am) * FULL + k0 + aj;
        __half* sa = sA + am * 40 + aj;
        *reinterpret_cast<uint4*>(sa)     = *reinterpret_cast<const uint4*>(ap);
        *reinterpret_cast<uint4*>(sa + 8) = *reinterpret_cast<const uint4*>(ap + 8);
        const __half* bp = B0 + (size_t)(k0 + bj) * (BSZ * 2 * HN * HD) + bd;
        *reinterpret_cast<uint4*>(sB + bj * 72 + bd) = *reinterpret_cast<const uint4*>(bp);
        __syncthreads();
#pragma unroll
        for (int kk = 0; kk < 2; kk++) {
            wmma::fragment<wmma::matrix_a, 16, 16, 16, __half, wmma::row_major> af[2];
            wmma::fragment<wmma::matrix_b, 16, 16, 16, __half, wmma::row_major> bf[2];
#pragma unroll
            for (int i = 0; i < 2; i++)
                wmma::load_matrix_sync(af[i], &sA[(wm * 32 + i * 16) * 40 + kk * 16], 40);
#pragma unroll
            for (int j = 0; j < 2; j++)
                wmma::load_matrix_sync(bf[j], &sB[(kk * 16) * 72 + wn * 32 + j * 16], 72);
#pragma unroll
            for (int i = 0; i < 2; i++)
#pragma unroll
                for (int j = 0; j < 2; j++)
                    wmma::mma_sync(acc[i][j], af[i], bf[j], acc[i][j]);
        }
        __syncthreads();
    }
    // fp16 epilogue via per-warp staging
    int rr = lid >> 1, cc = (lid & 1) * 8;
#pragma unroll
    for (int i = 0; i < 2; i++)
#pragma unroll
        for (int j = 0; j < 2; j++) {
            wmma::store_matrix_sync(&stg[warp][0], acc[i][j], 16, wmma::mem_row_major);
            __syncwarp();
            const float* src = &stg[warp][rr * 16 + cc];
            __half* dst = ctx + (size_t)((i0 + wm * 32 + i * 16 + rr) * BSZ + b) * DMODEL
                              + h * HD + wn * 32 + j * 16 + cc;
#pragma unroll
            for (int t = 0; t < 8; t += 2)
                *reinterpret_cast<__half2*>(dst + t) = __floats2half2_rn(src[t], src[t + 1]);
            __syncwarp();
        }
}

// ---------------------------------------------------------------------------
// Launch
// ---------------------------------------------------------------------------
extern "C" void kernel_launch(void* const* d_in, const int* in_sizes, int n_in,
                              void* d_out, int out_size)
{
    const float* inputs  = (const float*)d_in[0];
    const float* pos_emb = (const float*)d_in[1];
    const float* full_in = (const float*)d_in[2];
    const float* u       = (const float*)d_in[3];
    const float* v       = (const float*)d_in[4];
    const float* W_kv    = (const float*)d_in[6];
    const float* b_kv    = (const float*)d_in[7];
    const float* W_q     = (const float*)d_in[8];
    const float* b_q     = (const float*)d_in[9];
    const float* W_pos   = (const float*)d_in[10];
    const float* W_proj  = (const float*)d_in[12];
    const float* b_proj  = (const float*)d_in[13];
    float* out = (float*)d_out;

    float *q, *beff;
    __half *kv, *qu, *qv, *r, *ctx, *scores, *pos, *probs;
    cudaGetSymbolAddress((void**)&kv,     g_kv);
    cudaGetSymbolAddress((void**)&q,      g_q);
    cudaGetSymbolAddress((void**)&qu,     g_qu);
    cudaGetSymbolAddress((void**)&qv,     g_qv);
    cudaGetSymbolAddress((void**)&r,      g_r);
    cudaGetSymbolAddress((void**)&ctx,    g_ctx);
    cudaGetSymbolAddress((void**)&scores, g_scores_h);
    cudaGetSymbolAddress((void**)&pos,    g_pos_h);
    cudaGetSymbolAddress((void**)&probs,  g_probs_h);
    cudaGetSymbolAddress((void**)&beff,   g_beff);

    static int attr_set = 0;
    if (!attr_set) {
        cudaFuncSetAttribute(score_h, cudaFuncAttributeMaxDynamicSharedMemorySize,
                             SCORE_SMEM_BYTES);
        attr_set = 1;
    }

    // Projections -> fp16 intermediates
    gemm_f2h<<<dim3(2048 / 128, 8192 / 128), 256>>>(full_in, W_kv, kv, 8192, 2048, 1024);
    gemm_f2f<<<dim3(1024 / 128, 4096 / 128), 256>>>(inputs, W_q, q, 4096, 1024, 1024);
    gemm_f2h<<<dim3(1024 / 128, 2048 / 128), 256>>>(pos_emb, W_pos, r, 2048, 1024, 1024);

    quv_kernel<<<4096, 256>>>(q, b_q, u, v, qu, qv);
    beff_kernel<<<DMODEL / 256, 256>>>(b_kv, W_proj, b_proj, beff);

    // Scores (fp16 in/out)
    score_h<<<dim3(FULL / 128, CUR / 128, ZB), 256, SCORE_SMEM_BYTES>>>(qu, kv, scores, 0);
    score_h<<<dim3(FULL / 128, CUR / 128, ZB), 256, SCORE_SMEM_BYTES>>>(qv, r, pos, 1);

    // shift + mask + softmax -> fp16 probs
    softmax_kernel<<<dim3(CUR, ZB), 256>>>(scores, pos, probs);

    // ctx = probs @ val (fp16 out)
    ctx_h<<<dim3(CUR / 128, ZB), 256>>>(probs, kv, ctx);

    // out = ctx @ W_proj + b_eff
    gemm_h2f<<<dim3(1024 / 128, 4096 / 128), 256>>>(ctx, W_proj, out, 4096, 1024, 1024);
    bias_add_kernel<<<4096, 256>>>(out, beff);

    (void)in_sizes; (void)n_in; (void)out_size;
}

// round 11
// speedup vs baseline: 2.1622x; 1.2177x over previous
#include <cuda_runtime.h>
#include <cuda_fp16.h>
#include <mma.h>
#include <cstdint>

using namespace nvcuda;

// Problem constants
#define CUR    1024
#define FULL   2048
#define BSZ    4
#define DMODEL 1024
#define HN     16
#define HD     64
#define PREV   (FULL - CUR)      // 1024
#define ZB     (BSZ * HN)        // 64 batched heads
#define SCALE  0.125f            // 1/sqrt(64)

// ---------------------------------------------------------------------------
// Scratch
// ---------------------------------------------------------------------------
__device__ __half g_full_h [ (size_t)FULL * BSZ * DMODEL ];    // 8192 x 1024
__device__ __half g_in_h   [ (size_t)CUR * BSZ * DMODEL ];     // 4096 x 1024
__device__ __half g_pe_h   [ (size_t)FULL * DMODEL ];          // 2048 x 1024
__device__ __half g_Wkv_h  [ (size_t)DMODEL * 2 * DMODEL ];
__device__ __half g_Wq_h   [ (size_t)DMODEL * DMODEL ];
__device__ __half g_Wpos_h [ (size_t)DMODEL * DMODEL ];
__device__ __half g_Wproj_h[ (size_t)DMODEL * DMODEL ];

__device__ __half g_kv [ (size_t)FULL * BSZ * 2 * HN * HD ];   // 8192 x 2048
__device__ float  g_q  [ (size_t)CUR * BSZ * HN * HD ];        // fp32 pre-bias
__device__ __half g_qu [ (size_t)CUR * BSZ * HN * HD ];
__device__ __half g_qv [ (size_t)CUR * BSZ * HN * HD ];
__device__ __half g_r  [ (size_t)FULL * HN * HD ];
__device__ __half g_ctx[ (size_t)CUR * BSZ * HN * HD ];
__device__ __half g_scores_h[ (size_t)ZB * CUR * FULL ];
__device__ __half g_pos_h   [ (size_t)ZB * CUR * FULL ];
__device__ __half g_probs_h [ (size_t)ZB * CUR * FULL ];
__device__ float  g_beff[ DMODEL ];

#define H(x) __float2half_rn(x)

// cp.async helpers
__device__ __forceinline__ void cp16(void* smem, const void* gmem) {
    uint32_t s = (uint32_t)__cvta_generic_to_shared(smem);
    asm volatile("cp.async.cg.shared.global [%0], [%1], 16;\n" :: "r"(s), "l"(gmem));
}
#define CP_COMMIT asm volatile("cp.async.commit_group;\n" ::: "memory")
#define CP_WAIT1  asm volatile("cp.async.wait_group 1;\n" ::: "memory")
#define CP_WAIT0  asm volatile("cp.async.wait_group 0;\n" ::: "memory")

// ---------------------------------------------------------------------------
// fp32 -> fp16 convert
// ---------------------------------------------------------------------------
__global__ __launch_bounds__(256) void f2h_kernel(
    const float* __restrict__ src, __half* __restrict__ dst, int n4)
{
    int idx = blockIdx.x * 256 + threadIdx.x;
    if (idx < n4) {
        float4 v = reinterpret_cast<const float4*>(src)[idx];
        reinterpret_cast<__half2*>(dst)[idx * 2 + 0] = __floats2half2_rn(v.x, v.y);
        reinterpret_cast<__half2*>(dst)[idx * 2 + 1] = __floats2half2_rn(v.z, v.w);
    }
}

// ---------------------------------------------------------------------------
// FP16 GEMM, fp16 A/B, cp.async double-buffered: C = A @ B
// 128x128 tile, KC=32, 8 warps each 64x32. OUT_HALF selects epilogue.
// ---------------------------------------------------------------------------
template<bool OUT_HALF>
__global__ __launch_bounds__(256) void gemm_hh(
    const __half* __restrict__ A, const __half* __restrict__ B,
    void* __restrict__ Cv, int M, int N, int K)
{
    __shared__ __half sA[2][128 * 40];
    __shared__ __half sB[2][32 * 136];
    __shared__ float  stg[8][256];
    int tid = threadIdx.x, warp = tid >> 5, lid = tid & 31;
    int wm = warp >> 2, wn = warp & 3;
    int m0 = blockIdx.y * 128, n0 = blockIdx.x * 128;

    wmma::fragment<wmma::accumulator, 16, 16, 16, float> acc[4][2];
#pragma unroll
    for (int i = 0; i < 4; i++)
#pragma unroll
        for (int j = 0; j < 2; j++) wmma::fill_fragment(acc[i][j], 0.f);

    int am = tid >> 1,  ak = (tid & 1) * 16;
    int bk = tid >> 3,  bn = (tid & 7) * 16;
    const __half* Abase = A + (size_t)(m0 + am) * K + ak;
    const __half* Bbase = B + (size_t)bk * N + n0 + bn;

    int KT = K >> 5;
    // prologue: stage 0
    cp16(&sA[0][am * 40 + ak],     Abase);
    cp16(&sA[0][am * 40 + ak + 8], Abase + 8);
    cp16(&sB[0][bk * 136 + bn],     Bbase);
    cp16(&sB[0][bk * 136 + bn + 8], Bbase + 8);
    CP_COMMIT;

    for (int kt = 0; kt < KT; kt++) {
        if (kt + 1 < KT) {
            int buf = (kt + 1) & 1, k0 = (kt + 1) << 5;
            const __half* ap = Abase + k0;
            const __half* bp = Bbase + (size_t)k0 * N;
            cp16(&sA[buf][am * 40 + ak],     ap);
            cp16(&sA[buf][am * 40 + ak + 8], ap + 8);
            cp16(&sB[buf][bk * 136 + bn],     bp);
            cp16(&sB[buf][bk * 136 + bn + 8], bp + 8);
            CP_COMMIT;
            CP_WAIT1;
        } else {
            CP_WAIT0;
        }
        __syncthreads();
        int cb = kt & 1;
#pragma unroll
        for (int kk = 0; kk < 2; kk++) {
            wmma::fragment<wmma::matrix_a, 16, 16, 16, __half, wmma::row_major> af[4];
            wmma::fragment<wmma::matrix_b, 16, 16, 16, __half, wmma::row_major> bf[2];
#pragma unroll
            for (int i = 0; i < 4; i++)
                wmma::load_matrix_sync(af[i], &sA[cb][(wm * 64 + i * 16) * 40 + kk * 16], 40);
#pragma unroll
            for (int j = 0; j < 2; j++)
                wmma::load_matrix_sync(bf[j], &sB[cb][(kk * 16) * 136 + wn * 32 + j * 16], 136);
#pragma unroll
            for (int i = 0; i < 4; i++)
#pragma unroll
                for (int j = 0; j < 2; j++)
                    wmma::mma_sync(acc[i][j], af[i], bf[j], acc[i][j]);
        }
        __syncthreads();
    }

    if (OUT_HALF) {
        __half* C = reinterpret_cast<__half*>(Cv);
        int rr = lid >> 1, cc = (lid & 1) * 8;
#pragma unroll
        for (int i = 0; i < 4; i++)
#pragma unroll
            for (int j = 0; j < 2; j++) {
                wmma::store_matrix_sync(&stg[warp][0], acc[i][j], 16, wmma::mem_row_major);
                __syncwarp();
                const float* src = &stg[warp][rr * 16 + cc];
                __half* dst = C + (size_t)(m0 + wm * 64 + i * 16 + rr) * N
                                + n0 + wn * 32 + j * 16 + cc;
#pragma unroll
                for (int t = 0; t < 8; t += 2)
                    *reinterpret_cast<__half2*>(dst + t) = __floats2half2_rn(src[t], src[t + 1]);
                __syncwarp();
            }
    } else {
        float* C = reinterpret_cast<float*>(Cv);
#pragma unroll
        for (int i = 0; i < 4; i++)
#pragma unroll
            for (int j = 0; j < 2; j++)
                wmma::store_matrix_sync(
                    C + (size_t)(m0 + wm * 64 + i * 16) * N + n0 + wn * 32 + j * 16,
                    acc[i][j], N, wmma::mem_row_major);
    }
}

// ---------------------------------------------------------------------------
// qu/qv, beff, bias add (unchanged)
// ---------------------------------------------------------------------------
__global__ __launch_bounds__(256) void quv_kernel(
    const float* __restrict__ q, const float* __restrict__ b_q,
    const float* __restrict__ u, const float* __restrict__ v,
    __half* __restrict__ qu, __half* __restrict__ qv)
{
    int idx = blockIdx.x * 256 + threadIdx.x;
    int n4 = idx & 255;
    float4 qq = reinterpret_cast<const float4*>(q)[idx];
    float4 bb = reinterpret_cast<const float4*>(b_q)[n4];
    float4 uu = reinterpret_cast<const float4*>(u)[n4];
    float4 vv = reinterpret_cast<const float4*>(v)[n4];
    reinterpret_cast<__half2*>(qu)[idx * 2 + 0] = __floats2half2_rn(qq.x + bb.x + uu.x, qq.y + bb.y + uu.y);
    reinterpret_cast<__half2*>(qu)[idx * 2 + 1] = __floats2half2_rn(qq.z + bb.z + uu.z, qq.w + bb.w + uu.w);
    reinterpret_cast<__half2*>(qv)[idx * 2 + 0] = __floats2half2_rn(qq.x + bb.x + vv.x, qq.y + bb.y + vv.y);
    reinterpret_cast<__half2*>(qv)[idx * 2 + 1] = __floats2half2_rn(qq.z + bb.z + vv.z, qq.w + bb.w + vv.w);
}

__global__ __launch_bounds__(256) void beff_kernel(
    const float* __restrict__ b_kv, const float* __restrict__ W_proj,
    const float* __restrict__ b_proj, float* __restrict__ beff)
{
    int n = blockIdx.x * 256 + threadIdx.x;
    float acc = b_proj[n];
    for (int m = 0; m < DMODEL; m++)
        acc += b_kv[DMODEL + m] * W_proj[(size_t)m * DMODEL + n];
    beff[n] = acc;
}

__global__ __launch_bounds__(256) void bias_add_kernel(
    float* __restrict__ out, const float* __restrict__ beff)
{
    int idx = blockIdx.x * 256 + threadIdx.x;
    int n4 = idx & 255;
    float4 o = reinterpret_cast<float4*>(out)[idx];
    float4 b = reinterpret_cast<const float4*>(beff)[n4];
    o.x += b.x; o.y += b.y; o.z += b.z; o.w += b.w;
    reinterpret_cast<float4*>(out)[idx] = o;
}

// ---------------------------------------------------------------------------
// Score GEMM (fp16 in/out), single-shot K=64.  (R10 version)
// ---------------------------------------------------------------------------
#define SCORE_SMEM_BYTES (128 * 132 * 4)
__global__ __launch_bounds__(256) void score_h(
    const __half* __restrict__ QU, const __half* __restrict__ SRC,
    __half* __restrict__ OUT, int isPos)
{
    int i0 = blockIdx.y * 128, j0 = blockIdx.x * 128;
    if (!isPos && j0 >= i0 + 1152) return;
    if (isPos && (i0 + j0 + 254) < 1023) return;
    int z = blockIdx.z;
    int b = z >> 4, h = z & 15;
    const __half* A0 = QU + b * DMODEL + h * HD;
    const __half* B0 = isPos ? (SRC + h * HD) : (SRC + b * 2048 + h * HD);
    size_t ldB = isPos ? (size_t)(HN * HD) : (size_t)(BSZ * 2 * HN * HD);

    extern __shared__ char dynsm[];
    __half* sA = reinterpret_cast<__half*>(dynsm);           // 128 x 72
    __half* sB = sA + 128 * 72;
    float*  stage = reinterpret_cast<float*>(dynsm);

    int tid = threadIdx.x, warp = tid >> 5;
    int wm = warp >> 2, wn = warp & 3;

    wmma::fragment<wmma::accumulator, 16, 16, 16, float> acc[4][2];
#pragma unroll
    for (int i = 0; i < 4; i++)
#pragma unroll
        for (int j = 0; j < 2; j++) wmma::fill_fragment(acc[i][j], 0.f);

    int rm = tid >> 1, rk = (tid & 1) * 32;
    {
        const __half* ap = A0 + (size_t)(i0 + rm) * (BSZ * DMODEL) + rk;
        __half* sa = sA + rm * 72 + rk;
#pragma unroll
        for (int s = 0; s < 4; s++)
            *reinterpret_cast<uint4*>(sa + 8 * s) = *reinterpret_cast<const uint4*>(ap + 8 * s);
        const __half* bp = B0 + (size_t)(j0 + rm) * ldB + rk;
        __half* sb = sB + rm * 72 + rk;
#pragma unroll
        for (int s = 0; s < 4; s++)
            *reinterpret_cast<uint4*>(sb + 8 * s) = *reinterpret_cast<const uint4*>(bp + 8 * s);
    }
    __syncthreads();
#pragma unroll
    for (int kk = 0; kk < 4; kk++) {
        wmma::fragment<wmma::matrix_a, 16, 16, 16, __half, wmma::row_major> af[4];
        wmma::fragment<wmma::matrix_b, 16, 16, 16, __half, wmma::col_major> bf[2];
#pragma unroll
        for (int i = 0; i < 4; i++)
            wmma::load_matrix_sync(af[i], &sA[(wm * 64 + i * 16) * 72 + kk * 16], 72);
#pragma unroll
        for (int j = 0; j < 2; j++)
            wmma::load_matrix_sync(bf[j], &sB[(wn * 32 + j * 16) * 72 + kk * 16], 72);
#pragma unroll
        for (int i = 0; i < 4; i++)
#pragma unroll
            for (int j = 0; j < 2; j++)
                wmma::mma_sync(acc[i][j], af[i], bf[j], acc[i][j]);
    }
    __syncthreads();

#pragma unroll
    for (int i = 0; i < 4; i++)
#pragma unroll
        for (int j = 0; j < 2; j++)
            wmma::store_matrix_sync(&stage[(wm * 64 + i * 16) * 132 + wn * 32 + j * 16],
                                    acc[i][j], 132, wmma::mem_row_major);
    __syncthreads();

    __half* C0 = OUT + (size_t)z * CUR * FULL;
    int row = tid >> 1, cb = (tid & 1) * 64;
    __half* dst = C0 + (size_t)(i0 + row) * FULL + j0 + cb;
    const float* src = stage + row * 132 + cb;
#pragma unroll
    for (int t = 0; t < 64; t += 2)
        *reinterpret_cast<__half2*>(dst + t) = __floats2half2_rn(src[t], src[t + 1]);
}

// ---------------------------------------------------------------------------
// Fused rel_shift gather + mask + softmax: fp16 in/out.
// ---------------------------------------------------------------------------
__global__ __launch_bounds__(256) void softmax_kernel(
    const __half* __restrict__ cont, const __half* __restrict__ pos,
    __half* __restrict__ out)
{
    int i = blockIdx.x;
    int z = blockIdx.y;
    int tid = threadIdx.x;
    size_t rowOff = ((size_t)z * CUR + i) * FULL;
    const __half* c = cont + rowOff;
    const __half* p = pos + rowOff;
    int jmax  = i + PREV;
    int shift = CUR - 1 - i;

    float vals[8];
    float mx = -1e30f;
#pragma unroll
    for (int it = 0; it < 8; it++) {
        int j = tid + it * 256;
        float s = -1e30f;
        if (j <= jmax)
            s = (__half2float(c[j]) + __half2float(p[j + shift])) * SCALE;
        vals[it] = s;
        mx = fmaxf(mx, s);
    }
    __shared__ float redm[8];
    __shared__ float reds[8];
#pragma unroll
    for (int o = 16; o; o >>= 1) mx = fmaxf(mx, __shfl_xor_sync(0xffffffffu, mx, o));
    if ((tid & 31) == 0) redm[tid >> 5] = mx;
    __syncthreads();
    mx = redm[0];
#pragma unroll
    for (int w = 1; w < 8; w++) mx = fmaxf(mx, redm[w]);

    float sum = 0.f;
#pragma unroll
    for (int it = 0; it < 8; it++) {
        float e = __expf(vals[it] - mx);
        vals[it] = e;
        sum += e;
    }
#pragma unroll
    for (int o = 16; o; o >>= 1) sum += __shfl_xor_sync(0xffffffffu, sum, o);
    if ((tid & 31) == 0) reds[tid >> 5] = sum;
    __syncthreads();
    sum = 0.f;
#pragma unroll
    for (int w = 0; w < 8; w++) sum += reds[w];
    float inv = 1.f / sum;

    __half* o = out + rowOff;
#pragma unroll
    for (int it = 0; it < 8; it++) {
        int j = tid + it * 256;
        o[j] = (j <= jmax) ? H(vals[it] * inv) : __half(0.f);
    }
}

// ---------------------------------------------------------------------------
// Context GEMM fp16, cp.async double-buffered. K truncated at i0+1152.
// Block 128(i) x 64(d), KC=32.
// ---------------------------------------------------------------------------
__global__ __launch_bounds__(256) void ctx_h(
    const __half* __restrict__ probs, const __half* __restrict__ kv,
    __half* __restrict__ ctx)
{
    int z = blockIdx.y;
    int b = z >> 4, h = z & 15;
    int i0 = blockIdx.x * 128;
    const __half* A0 = probs + (size_t)z * CUR * FULL;
    const __half* B0 = kv + (size_t)b * 2048 + DMODEL + h * HD;

    __shared__ __half sA[2][128 * 40];
    __shared__ __half sB[2][32 * 72];
    __shared__ float  stg[8][256];
    int tid = threadIdx.x, warp = tid >> 5, lid = tid & 31;
    int wm = warp >> 1, wn = warp & 1;

    wmma::fragment<wmma::accumulator, 16, 16, 16, float> acc[2][2];
#pragma unroll
    for (int i = 0; i < 2; i++)
#pragma unroll
        for (int j = 0; j < 2; j++) wmma::fill_fragment(acc[i][j], 0.f);

    int am = tid >> 1, aj = (tid & 1) * 16;
    int bj = tid >> 3, bd = (tid & 7) * 8;
    const __half* Abase = A0 + (size_t)(i0 + am) * FULL + aj;
    const __half* Bbase = B0 + (size_t)bj * (BSZ * 2 * HN * HD) + bd;
    const size_t bstr = (size_t)(BSZ * 2 * HN * HD);

    int kmax = i0 + 1152;  if (kmax > FULL) kmax = FULL;
    int KT = kmax >> 5;

    cp16(&sA[0][am * 40 + aj],     Abase);
    cp16(&sA[0][am * 40 + aj + 8], Abase + 8);
    cp16(&sB[0][bj * 72 + bd],     Bbase);
    CP_COMMIT;

    for (int kt = 0; kt < KT; kt++) {
        if (kt + 1 < KT) {
            int buf = (kt + 1) & 1, k0 = (kt + 1) << 5;
            const __half* ap = Abase + k0;
            const __half* bp = Bbase + (size_t)k0 * bstr;
            cp16(&sA[buf][am * 40 + aj],     ap);
            cp16(&sA[buf][am * 40 + aj + 8], ap + 8);
            cp16(&sB[buf][bj * 72 + bd],     bp);
            CP_COMMIT;
            CP_WAIT1;
        } else {
            CP_WAIT0;
        }
        __syncthreads();
        int cb = kt & 1;
#pragma unroll
        for (int kk = 0; kk < 2; kk++) {
            wmma::fragment<wmma::matrix_a, 16, 16, 16, __half, wmma::row_major> af[2];
            wmma::fragment<wmma::matrix_b, 16, 16, 16, __half, wmma::row_major> bf[2];
#pragma unroll
            for (int i = 0; i < 2; i++)
                wmma::load_matrix_sync(af[i], &sA[cb][(wm * 32 + i * 16) * 40 + kk * 16], 40);
#pragma unroll
            for (int j = 0; j < 2; j++)
                wmma::load_matrix_sync(bf[j], &sB[cb][(kk * 16) * 72 + wn * 32 + j * 16], 72);
#pragma unroll
            for (int i = 0; i < 2; i++)
#pragma unroll
                for (int j = 0; j < 2; j++)
                    wmma::mma_sync(acc[i][j], af[i], bf[j], acc[i][j]);
        }
        __syncthreads();
    }
    int rr = lid >> 1, cc = (lid & 1) * 8;
#pragma unroll
    for (int i = 0; i < 2; i++)
#pragma unroll
        for (int j = 0; j < 2; j++) {
            wmma::store_matrix_sync(&stg[warp][0], acc[i][j], 16, wmma::mem_row_major);
            __syncwarp();
            const float* src = &stg[warp][rr * 16 + cc];
            __half* dst = ctx + (size_t)((i0 + wm * 32 + i * 16 + rr) * BSZ + b) * DMODEL
                              + h * HD + wn * 32 + j * 16 + cc;
#pragma unroll
            for (int t = 0; t < 8; t += 2)
                *reinterpret_cast<__half2*>(dst + t) = __floats2half2_rn(src[t], src[t + 1]);
            __syncwarp();
        }
}

// ---------------------------------------------------------------------------
// Launch
// ---------------------------------------------------------------------------
extern "C" void kernel_launch(void* const* d_in, const int* in_sizes, int n_in,
                              void* d_out, int out_size)
{
    const float* inputs  = (const float*)d_in[0];
    const float* pos_emb = (const float*)d_in[1];
    const float* full_in = (const float*)d_in[2];
    const float* u       = (const float*)d_in[3];
    const float* v       = (const float*)d_in[4];
    const float* W_kv    = (const float*)d_in[6];
    const float* b_kv    = (const float*)d_in[7];
    const float* W_q     = (const float*)d_in[8];
    const float* b_q     = (const float*)d_in[9];
    const float* W_pos   = (const float*)d_in[10];
    const float* W_proj  = (const float*)d_in[12];
    const float* b_proj  = (const float*)d_in[13];
    float* out = (float*)d_out;

    float *q, *beff;
    __half *fullh, *inh, *peh, *Wkvh, *Wqh, *Wposh, *Wprojh;
    __half *kv, *qu, *qv, *r, *ctx, *scores, *pos, *probs;
    cudaGetSymbolAddress((void**)&fullh,  g_full_h);
    cudaGetSymbolAddress((void**)&inh,    g_in_h);
    cudaGetSymbolAddress((void**)&peh,    g_pe_h);
    cudaGetSymbolAddress((void**)&Wkvh,   g_Wkv_h);
    cudaGetSymbolAddress((void**)&Wqh,    g_Wq_h);
    cudaGetSymbolAddress((void**)&Wposh,  g_Wpos_h);
    cudaGetSymbolAddress((void**)&Wprojh, g_Wproj_h);
    cudaGetSymbolAddress((void**)&kv,     g_kv);
    cudaGetSymbolAddress((void**)&q,      g_q);
    cudaGetSymbolAddress((void**)&qu,     g_qu);
    cudaGetSymbolAddress((void**)&qv,     g_qv);
    cudaGetSymbolAddress((void**)&r,      g_r);
    cudaGetSymbolAddress((void**)&ctx,    g_ctx);
    cudaGetSymbolAddress((void**)&scores, g_scores_h);
    cudaGetSymbolAddress((void**)&pos,    g_pos_h);
    cudaGetSymbolAddress((void**)&probs,  g_probs_h);
    cudaGetSymbolAddress((void**)&beff,   g_beff);

    static int attr_set = 0;
    if (!attr_set) {
        cudaFuncSetAttribute(score_h, cudaFuncAttributeMaxDynamicSharedMemorySize,
                             SCORE_SMEM_BYTES);
        attr_set = 1;
    }

    // fp32 -> fp16 converts (one-time per call; same rounding as old smem fills)
    f2h_kernel<<<(8192 * 1024 / 4) / 256, 256>>>(full_in, fullh, 8192 * 1024 / 4);
    f2h_kernel<<<(4096 * 1024 / 4) / 256, 256>>>(inputs, inh, 4096 * 1024 / 4);
    f2h_kernel<<<(2048 * 1024 / 4) / 256, 256>>>(pos_emb, peh, 2048 * 1024 / 4);
    f2h_kernel<<<(1024 * 2048 / 4) / 256, 256>>>(W_kv, Wkvh, 1024 * 2048 / 4);
    f2h_kernel<<<(1024 * 1024 / 4) / 256, 256>>>(W_q, Wqh, 1024 * 1024 / 4);
    f2h_kernel<<<(1024 * 1024 / 4) / 256, 256>>>(W_pos, Wposh, 1024 * 1024 / 4);
    f2h_kernel<<<(1024 * 1024 / 4) / 256, 256>>>(W_proj, Wprojh, 1024 * 1024 / 4);

    // Projections (fp16 in, cp.async pipelined)
    gemm_hh<true ><<<dim3(2048 / 128, 8192 / 128), 256>>>(fullh, Wkvh, kv, 8192, 2048, 1024);
    gemm_hh<false><<<dim3(1024 / 128, 4096 / 128), 256>>>(inh, Wqh, q, 4096, 1024, 1024);
    gemm_hh<true ><<<dim3(1024 / 128, 2048 / 128), 256>>>(peh, Wposh, r, 2048, 1024, 1024);

    quv_kernel<<<4096, 256>>>(q, b_q, u, v, qu, qv);
    beff_kernel<<<DMODEL / 256, 256>>>(b_kv, W_proj, b_proj, beff);

    // Scores (fp16 in/out)
    score_h<<<dim3(FULL / 128, CUR / 128, ZB), 256, SCORE_SMEM_BYTES>>>(qu, kv, scores, 0);
    score_h<<<dim3(FULL / 128, CUR / 128, ZB), 256, SCORE_SMEM_BYTES>>>(qv, r, pos, 1);

    // shift + mask + softmax -> fp16 probs
    softmax_kernel<<<dim3(CUR, ZB), 256>>>(scores, pos, probs);

    // ctx = probs @ val (cp.async pipelined)
    ctx_h<<<dim3(CUR / 128, ZB), 256>>>(probs, kv, ctx);

    // out = ctx @ W_proj + b_eff
    gemm_hh<false><<<dim3(1024 / 128, 4096 / 128), 256>>>(ctx, Wprojh, out, 4096, 1024, 1024);
    bias_add_kernel<<<4096, 256>>>(out, beff);

    (void)in_sizes; (void)n_in; (void)out_size;
}